// round 13
// baseline (speedup 1.0000x reference)
#include <cuda_runtime.h>
#include <stdint.h>

#define Bb 8
#define NF 128
#define Ee 3072
#define Uu 4096
#define UT 64
#define NTILES (Uu / UT)          // 64
#define TCAP 512
#define BK 128                    // per-class bucket capacity (expected ~17, 8 classes)

#define VL_BLOCKS Bb                              // 8 vlist blocks (first)
#define TR_BLOCKS (Bb * (Ee / 32) * (NF / 32))    // 3072 transpose blocks
#define SC_BLOCKS (Bb * (Ee / 8))                 // 3072 scan blocks

// Scratch (static __device__ arrays; no allocation at runtime)
__device__ unsigned short g_vlist[Bb * Ee];                 // v index of e-th true dst slot
__device__ float g_ft[(size_t)Bb * Ee * NF];                // transposed features [b][e][n]
__device__ int   g_cnt[Bb * NTILES];                        // per-(b,utile) hit counts
__device__ uint2 g_list[(size_t)Bb * NTILES * TCAP];        // hit entries: (e<<6|ulocal, w bits)
__device__ int   g_done;                                    // vlist-ready flag (reset by accum)

// ------------- kernel 1: vlist (8) + transpose (3072) + scan (3072), one launch -------------
__global__ __launch_bounds__(256) void mega_kernel(
    const float* __restrict__ W, const float* __restrict__ features,
    const unsigned char* __restrict__ dstraw) {
    int bid = blockIdx.x;
    int tid = threadIdx.x;

    if (bid < VL_BLOCKS) {
        // ---- vlist for batch bid: prefix-scan dst mask; zero hit counters ----
        __shared__ int s_nz;
        __shared__ int wsum[8];
        int b = bid;
        if (tid < NTILES) g_cnt[b * NTILES + tid] = 0;   // graph-replay safe reset

        // dtype detection: nonzero bytes sampled from first 4096 bytes.
        if (tid == 0) s_nz = 0;
        __syncthreads();
        int nz = (dstraw[tid] != 0) + (dstraw[1024 + tid] != 0) +
                 (dstraw[2048 + tid] != 0) + (dstraw[3072 + tid] != 0);
#pragma unroll
        for (int off = 16; off; off >>= 1) nz += __shfl_down_sync(0xffffffffu, nz, off);
        if ((tid & 31) == 0) atomicAdd(&s_nz, nz);
        __syncthreads();
        bool is_byte = (s_nz > 512);

        // each thread handles 16 consecutive mask elements
        int v0 = tid * 16;
        unsigned m16 = 0;
        if (is_byte) {
            uint4 r = *(const uint4*)(dstraw + (size_t)b * Uu + v0);
            unsigned wds[4] = {r.x, r.y, r.z, r.w};
#pragma unroll
            for (int w = 0; w < 4; ++w)
#pragma unroll
                for (int k = 0; k < 4; ++k)
                    if ((wds[w] >> (8 * k)) & 0xffu) m16 |= 1u << (w * 4 + k);
        } else {
            const uint4* d32 = (const uint4*)dstraw;
#pragma unroll
            for (int w = 0; w < 4; ++w) {
                uint4 r = d32[((size_t)b * Uu + v0) / 4 + w];
                if (r.x) m16 |= 1u << (w * 4 + 0);
                if (r.y) m16 |= 1u << (w * 4 + 1);
                if (r.z) m16 |= 1u << (w * 4 + 2);
                if (r.w) m16 |= 1u << (w * 4 + 3);
            }
        }
        int c = __popc(m16);
        int incl = c;
#pragma unroll
        for (int off = 1; off < 32; off <<= 1) {
            int y = __shfl_up_sync(0xffffffffu, incl, off);
            if ((tid & 31) >= off) incl += y;
        }
        if ((tid & 31) == 31) wsum[tid >> 5] = incl;
        __syncthreads();
        if (tid < 8) {
            int s = wsum[tid];
#pragma unroll
            for (int off = 1; off < 8; off <<= 1) {
                int y = __shfl_up_sync(0xffu, s, off);
                if (tid >= off) s += y;
            }
            wsum[tid] = s;
        }
        __syncthreads();
        int base = ((tid >> 5) ? wsum[(tid >> 5) - 1] : 0) + incl - c;
#pragma unroll
        for (int k = 0; k < 16; ++k) {
            if ((m16 >> k) & 1u) {
                if (base < Ee) g_vlist[b * Ee + base] = (unsigned short)(v0 + k);
                ++base;
            }
        }
        // publish: vlist for this batch is ready
        __syncthreads();
        if (tid == 0) {
            __threadfence();
            atomicAdd(&g_done, 1);
        }
        return;
    }

    if (bid < VL_BLOCKS + TR_BLOCKS) {
        // ---- transpose features [B,NF,E] -> g_ft [B,E,NF], 128-bit both sides ----
        __shared__ float tile[32][33];
        int tb  = bid - VL_BLOCKS;
        int b   = tb / 384;                 // 384 = (Ee/32)*(NF/32)
        int rem = tb % 384;
        int e0  = (rem % 96) * 32;
        int n0  = (rem / 96) * 32;
        {
            int n_idx = tid >> 3;
            int e_idx = (tid & 7) * 4;
            float4 v = *(const float4*)(features +
                          (size_t)b * NF * Ee + (size_t)(n0 + n_idx) * Ee + e0 + e_idx);
            tile[e_idx + 0][n_idx] = v.x;
            tile[e_idx + 1][n_idx] = v.y;
            tile[e_idx + 2][n_idx] = v.z;
            tile[e_idx + 3][n_idx] = v.w;
        }
        __syncthreads();
        {
            int e_w = tid >> 3;
            int n_w = (tid & 7) * 4;
            float4 v;
            v.x = tile[e_w][n_w + 0];
            v.y = tile[e_w][n_w + 1];
            v.z = tile[e_w][n_w + 2];
            v.w = tile[e_w][n_w + 3];
            *(float4*)(g_ft + (size_t)b * Ee * NF + (size_t)(e0 + e_w) * NF + n0 + n_w) = v;
        }
        return;
    }

    // ---- scan: wait for vlist, then one warp streams one full 16KB row of W ----
    __shared__ int s_ready;
    if (tid == 0) {
        while (atomicAdd(&g_done, 0) < Bb) { /* spin (vlist blocks are wave-1) */ }
        __threadfence();
        s_ready = 1;
    }
    __syncthreads();
    (void)s_ready;

    int sbid = bid - (VL_BLOCKS + TR_BLOCKS);
    int b    = sbid / (Ee / 8);
    int eblk = sbid % (Ee / 8);
    int warp = tid >> 5;
    int lane = tid & 31;
    int e    = eblk * 8 + warp;

    int v = g_vlist[b * Ee + e];
    const float4* row = (const float4*)(W + ((size_t)b * Uu + v) * Uu);

#pragma unroll 1
    for (int i0 = 0; i0 < 32; i0 += 8) {
        float4 x[8];
#pragma unroll
        for (int j = 0; j < 8; ++j)
            x[j] = __ldcs(&row[(i0 + j) * 32 + lane]);   // streaming: read-once data

#define ORW(v4) (__float_as_uint((v4).x) | __float_as_uint((v4).y) | \
                 __float_as_uint((v4).z) | __float_as_uint((v4).w))
        unsigned any = (ORW(x[0]) | ORW(x[1]) | ORW(x[2]) | ORW(x[3])) |
                       (ORW(x[4]) | ORW(x[5]) | ORW(x[6]) | ORW(x[7]));
        if (any) {
#pragma unroll
            for (int j = 0; j < 8; ++j) {
                float vals[4] = {x[j].x, x[j].y, x[j].z, x[j].w};
#pragma unroll
                for (int k = 0; k < 4; ++k) {
                    if (__float_as_uint(vals[k]) != 0u) {
                        int u  = ((i0 + j) * 32 + lane) * 4 + k;
                        int ut = u >> 6;
                        int pos = atomicAdd(&g_cnt[b * NTILES + ut], 1);
                        if (pos < TCAP)
                            g_list[((size_t)(b * NTILES + ut)) * TCAP + pos] =
                                make_uint2(((unsigned)e << 6) | (unsigned)(u & 63),
                                           __float_as_uint(vals[k]));
                    }
                }
            }
        }
    }
}

// ---------------- kernel 2: accumulate — 8-class bucketing, atomic-free RMW ----------------
__global__ __launch_bounds__(256) void accum_kernel(
    const float* __restrict__ occ, float* __restrict__ out) {
    __shared__ float s_acc[UT * 132];
    __shared__ float s_rocc[UT];
    __shared__ uint2 s_bkt[8 * BK];
    __shared__ int   s_bcnt[8];

    int b   = blockIdx.y;
    int ut  = blockIdx.x;
    int u0  = ut * UT;
    int tid = threadIdx.x;
    int warp = tid >> 5;     // 0..7
    int lane = tid & 31;
    int n0 = lane * 4;

    // reset the vlist flag for the NEXT graph replay (stream-ordered)
    if (b == 0 && ut == 0 && tid == 0) g_done = 0;

    // issue the count load FIRST so its latency overlaps the zero-init
    int cnt_raw = g_cnt[b * NTILES + ut];

    if (tid < 8) s_bcnt[tid] = 0;
    for (int i = tid; i < UT * 132; i += 256) s_acc[i] = 0.f;
    if (tid < UT) s_rocc[tid] = 1.0f / occ[(size_t)b * Uu + u0 + tid];
    __syncthreads();

    int cnt = min(cnt_raw, TCAP);
    const uint2* list = &g_list[((size_t)(b * NTILES + ut)) * TCAP];

    // phase 1: bucket entries by u-class (u & 7); atomics only on 8 counters
    for (int i = tid; i < cnt; i += 256) {
        uint2 ent = __ldg(&list[i]);
        int c = ent.x & 7;
        int pos = atomicAdd(&s_bcnt[c], 1);
        if (pos < BK) s_bkt[c * BK + pos] = ent;
    }
    __syncthreads();

    // phase 2: warp w drains bucket w with plain (atomic-free) RMW.
    // class-disjoint u across warps + lane-disjoint n0 within warp = no races.
    {
        const float* ftb = g_ft + (size_t)b * Ee * NF + n0;
        const uint2* bkt = &s_bkt[warp * BK];
        int m = min(s_bcnt[warp], BK);

#define APPLY(ee, ff)                                                     \
        {                                                                 \
            int u = (ee).x & 63;                                          \
            float w = __uint_as_float((ee).y);                            \
            float4* ap = (float4*)&s_acc[u * 132 + n0];                   \
            float4 a = *ap;                                               \
            a.x += w * (ff).x; a.y += w * (ff).y;                         \
            a.z += w * (ff).z; a.w += w * (ff).w;                         \
            *ap = a;                                                      \
        }

        int j = 0;
        for (; j + 8 <= m; j += 8) {     // 8-wide gather batching (MLP=8)
            uint2 ee[8];
            float4 ff[8];
#pragma unroll
            for (int k = 0; k < 8; ++k) ee[k] = bkt[j + k];
#pragma unroll
            for (int k = 0; k < 8; ++k)
                ff[k] = *(const float4*)&ftb[(size_t)(ee[k].x >> 6) * NF];
#pragma unroll
            for (int k = 0; k < 8; ++k) APPLY(ee[k], ff[k]);
        }
        if (j < m) {                     // tail: up to 7 entries, still batched
            uint2 ee[8];
            float4 ff[8];
            int r = m - j;
#pragma unroll
            for (int k = 0; k < 8; ++k) if (k < r) ee[k] = bkt[j + k];
#pragma unroll
            for (int k = 0; k < 8; ++k)
                if (k < r) ff[k] = *(const float4*)&ftb[(size_t)(ee[k].x >> 6) * NF];
#pragma unroll
            for (int k = 0; k < 8; ++k) if (k < r) APPLY(ee[k], ff[k]);
        }
    }
    __syncthreads();

    // epilogue: multiply by 1/occ, coalesced store
    int u  = tid & (UT - 1);
    int nb = tid >> 6;          // 0..3
    float r = s_rocc[u];
#pragma unroll
    for (int i = 0; i < (UT * NF / 256); ++i) {   // 32 iters
        int n = 4 * i + nb;
        out[((size_t)(b * NF + n)) * Uu + u0 + u] = s_acc[u * 132 + n] * r;
    }
}

extern "C" void kernel_launch(void* const* d_in, const int* in_sizes, int n_in,
                              void* d_out, int out_size) {
    const float* features          = (const float*)d_in[0];
    const float* unroll_mat        = (const float*)d_in[1];
    const float* occurrences       = (const float*)d_in[2];
    const unsigned char* dst_masks = (const unsigned char*)d_in[3];
    float* out = (float*)d_out;

    mega_kernel<<<VL_BLOCKS + TR_BLOCKS + SC_BLOCKS, 256>>>(unroll_mat, features, dst_masks);
    accum_kernel<<<dim3(NTILES, Bb), 256>>>(occurrences, out);
}

// round 14
// speedup vs baseline: 1.0423x; 1.0423x over previous
#include <cuda_runtime.h>
#include <stdint.h>

#define Bb 8
#define NF 128
#define Ee 3072
#define Uu 4096
#define UT 64
#define NTILES (Uu / UT)          // 64
#define BK 64                     // per-class list capacity (expected ~17, 8 classes)

#define VL_BLOCKS Bb                              // 8 vlist blocks (first)
#define TR_BLOCKS (Bb * (Ee / 32) * (NF / 32))    // 3072 transpose blocks

// Scratch (static __device__ arrays; no allocation at runtime)
__device__ unsigned short g_vlist[Bb * Ee];                 // v index of e-th true dst slot
__device__ float g_ft[(size_t)Bb * Ee * NF];                // transposed features [b][e][n]
__device__ int   g_cnt[Bb * NTILES * 8];                    // per-(b,utile,class) hit counts
__device__ uint2 g_list[(size_t)Bb * NTILES * 8 * BK];      // entries: (e<<6|ulocal, w bits)

// ---------------- kernel 1: vlist blocks (first 8) + float4 transpose blocks ----------------
__global__ __launch_bounds__(256) void prep_kernel(
    const float* __restrict__ features, const unsigned char* __restrict__ dstraw) {
    int bid = blockIdx.x;
    int tid = threadIdx.x;

    if (bid < VL_BLOCKS) {
        // ---- vlist for batch bid: prefix-scan dst mask; zero hit counters ----
        __shared__ int s_nz;
        __shared__ int wsum[8];
        int b = bid;
        // reset this batch's 512 class counters (graph-replay safe)
        g_cnt[b * NTILES * 8 + tid] = 0;
        g_cnt[b * NTILES * 8 + 256 + tid] = 0;

        // dtype detection: nonzero bytes sampled from first 4096 bytes.
        if (tid == 0) s_nz = 0;
        __syncthreads();
        int nz = (dstraw[tid] != 0) + (dstraw[1024 + tid] != 0) +
                 (dstraw[2048 + tid] != 0) + (dstraw[3072 + tid] != 0);
#pragma unroll
        for (int off = 16; off; off >>= 1) nz += __shfl_down_sync(0xffffffffu, nz, off);
        if ((tid & 31) == 0) atomicAdd(&s_nz, nz);
        __syncthreads();
        bool is_byte = (s_nz > 512);

        // each thread handles 16 consecutive mask elements
        int v0 = tid * 16;
        unsigned m16 = 0;
        if (is_byte) {
            uint4 r = *(const uint4*)(dstraw + (size_t)b * Uu + v0);
            unsigned wds[4] = {r.x, r.y, r.z, r.w};
#pragma unroll
            for (int w = 0; w < 4; ++w)
#pragma unroll
                for (int k = 0; k < 4; ++k)
                    if ((wds[w] >> (8 * k)) & 0xffu) m16 |= 1u << (w * 4 + k);
        } else {
            const uint4* d32 = (const uint4*)dstraw;
#pragma unroll
            for (int w = 0; w < 4; ++w) {
                uint4 r = d32[((size_t)b * Uu + v0) / 4 + w];
                if (r.x) m16 |= 1u << (w * 4 + 0);
                if (r.y) m16 |= 1u << (w * 4 + 1);
                if (r.z) m16 |= 1u << (w * 4 + 2);
                if (r.w) m16 |= 1u << (w * 4 + 3);
            }
        }
        int c = __popc(m16);
        int incl = c;
#pragma unroll
        for (int off = 1; off < 32; off <<= 1) {
            int y = __shfl_up_sync(0xffffffffu, incl, off);
            if ((tid & 31) >= off) incl += y;
        }
        if ((tid & 31) == 31) wsum[tid >> 5] = incl;
        __syncthreads();
        if (tid < 8) {
            int s = wsum[tid];
#pragma unroll
            for (int off = 1; off < 8; off <<= 1) {
                int y = __shfl_up_sync(0xffu, s, off);
                if (tid >= off) s += y;
            }
            wsum[tid] = s;
        }
        __syncthreads();
        int base = ((tid >> 5) ? wsum[(tid >> 5) - 1] : 0) + incl - c;
#pragma unroll
        for (int k = 0; k < 16; ++k) {
            if ((m16 >> k) & 1u) {
                if (base < Ee) g_vlist[b * Ee + base] = (unsigned short)(v0 + k);
                ++base;
            }
        }
        return;
    }

    // ---- transpose features [B,NF,E] -> g_ft [B,E,NF], 128-bit both sides ----
    __shared__ float tile[32][33];
    int tb  = bid - VL_BLOCKS;
    int b   = tb / 384;                 // 384 = (Ee/32)*(NF/32)
    int rem = tb % 384;
    int e0  = (rem % 96) * 32;
    int n0  = (rem / 96) * 32;
    {
        int n_idx = tid >> 3;
        int e_idx = (tid & 7) * 4;
        float4 v = *(const float4*)(features +
                      (size_t)b * NF * Ee + (size_t)(n0 + n_idx) * Ee + e0 + e_idx);
        tile[e_idx + 0][n_idx] = v.x;
        tile[e_idx + 1][n_idx] = v.y;
        tile[e_idx + 2][n_idx] = v.z;
        tile[e_idx + 3][n_idx] = v.w;
    }
    __syncthreads();
    {
        int e_w = tid >> 3;
        int n_w = (tid & 7) * 4;
        float4 v;
        v.x = tile[e_w][n_w + 0];
        v.y = tile[e_w][n_w + 1];
        v.z = tile[e_w][n_w + 2];
        v.w = tile[e_w][n_w + 3];
        *(float4*)(g_ft + (size_t)b * Ee * NF + (size_t)(e0 + e_w) * NF + n0 + n_w) = v;
    }
}

// ------- kernel 2: scan — one warp streams one 16KB row; hits go to class lists -------
__global__ __launch_bounds__(256) void scan_kernel(const float* __restrict__ W) {
    int b    = blockIdx.y;
    int warp = threadIdx.x >> 5;
    int lane = threadIdx.x & 31;
    int e    = blockIdx.x * 8 + warp;

    int v = g_vlist[b * Ee + e];
    const float4* row = (const float4*)(W + ((size_t)b * Uu + v) * Uu);

#pragma unroll 1
    for (int i0 = 0; i0 < 32; i0 += 8) {
        float4 x[8];
#pragma unroll
        for (int j = 0; j < 8; ++j)
            x[j] = __ldcs(&row[(i0 + j) * 32 + lane]);   // streaming: read-once data

#define ORW(v4) (__float_as_uint((v4).x) | __float_as_uint((v4).y) | \
                 __float_as_uint((v4).z) | __float_as_uint((v4).w))
        unsigned any = (ORW(x[0]) | ORW(x[1]) | ORW(x[2]) | ORW(x[3])) |
                       (ORW(x[4]) | ORW(x[5]) | ORW(x[6]) | ORW(x[7]));
        if (any) {
#pragma unroll
            for (int j = 0; j < 8; ++j) {
                float vals[4] = {x[j].x, x[j].y, x[j].z, x[j].w};
#pragma unroll
                for (int k = 0; k < 4; ++k) {
                    if (__float_as_uint(vals[k]) != 0u) {
                        int u   = ((i0 + j) * 32 + lane) * 4 + k;
                        int ut  = u >> 6;
                        int cls = u & 7;
                        int slot = (b * NTILES + ut) * 8 + cls;
                        int pos = atomicAdd(&g_cnt[slot], 1);
                        if (pos < BK)
                            g_list[(size_t)slot * BK + pos] =
                                make_uint2(((unsigned)e << 6) | (unsigned)(u & 63),
                                           __float_as_uint(vals[k]));
                    }
                }
            }
        }
    }
}

// -------- kernel 3: accumulate — pre-classed lists, atomic-free RMW, 2 barriers --------
__global__ __launch_bounds__(256) void accum_kernel(
    const float* __restrict__ occ, float* __restrict__ out) {
    __shared__ float s_acc[UT * 132];
    __shared__ float s_rocc[UT];

    int b   = blockIdx.y;
    int ut  = blockIdx.x;
    int u0  = ut * UT;
    int tid = threadIdx.x;
    int warp = tid >> 5;     // 0..7 = u-class
    int lane = tid & 31;
    int n0 = lane * 4;

    // issue count load FIRST so its latency overlaps the zero-init
    int m_raw = g_cnt[(b * NTILES + ut) * 8 + warp];

    for (int i = tid; i < UT * 132; i += 256) s_acc[i] = 0.f;
    if (tid < UT) s_rocc[tid] = 1.0f / occ[(size_t)b * Uu + u0 + tid];
    __syncthreads();

    // warp w drains its class list directly from global (uniform broadcast loads).
    // class-disjoint u across warps + lane-disjoint n0 within warp = no races.
    {
        const float* ftb = g_ft + (size_t)b * Ee * NF + n0;
        const uint2* clist = &g_list[(size_t)((b * NTILES + ut) * 8 + warp) * BK];
        int m = min(m_raw, BK);

#define APPLY(ee, ff)                                                     \
        {                                                                 \
            int u = (ee).x & 63;                                          \
            float w = __uint_as_float((ee).y);                            \
            float4* ap = (float4*)&s_acc[u * 132 + n0];                   \
            float4 a = *ap;                                               \
            a.x += w * (ff).x; a.y += w * (ff).y;                         \
            a.z += w * (ff).z; a.w += w * (ff).w;                         \
            *ap = a;                                                      \
        }

        int j = 0;
        for (; j + 8 <= m; j += 8) {     // 8-wide gather batching (MLP=8)
            uint2 ee[8];
            float4 ff[8];
#pragma unroll
            for (int k = 0; k < 8; ++k) ee[k] = __ldg(&clist[j + k]);
#pragma unroll
            for (int k = 0; k < 8; ++k)
                ff[k] = *(const float4*)&ftb[(size_t)(ee[k].x >> 6) * NF];
#pragma unroll
            for (int k = 0; k < 8; ++k) APPLY(ee[k], ff[k]);
        }
        if (j < m) {                     // tail: up to 7 entries, still batched
            uint2 ee[8];
            float4 ff[8];
            int r = m - j;
#pragma unroll
            for (int k = 0; k < 8; ++k) if (k < r) ee[k] = __ldg(&clist[j + k]);
#pragma unroll
            for (int k = 0; k < 8; ++k)
                if (k < r) ff[k] = *(const float4*)&ftb[(size_t)(ee[k].x >> 6) * NF];
#pragma unroll
            for (int k = 0; k < 8; ++k) if (k < r) APPLY(ee[k], ff[k]);
        }
    }
    __syncthreads();

    // epilogue: multiply by 1/occ, coalesced store
    int u  = tid & (UT - 1);
    int nb = tid >> 6;          // 0..3
    float r = s_rocc[u];
#pragma unroll
    for (int i = 0; i < (UT * NF / 256); ++i) {   // 32 iters
        int n = 4 * i + nb;
        out[((size_t)(b * NF + n)) * Uu + u0 + u] = s_acc[u * 132 + n] * r;
    }
}

extern "C" void kernel_launch(void* const* d_in, const int* in_sizes, int n_in,
                              void* d_out, int out_size) {
    const float* features          = (const float*)d_in[0];
    const float* unroll_mat        = (const float*)d_in[1];
    const float* occurrences       = (const float*)d_in[2];
    const unsigned char* dst_masks = (const unsigned char*)d_in[3];
    float* out = (float*)d_out;

    prep_kernel<<<VL_BLOCKS + TR_BLOCKS, 256>>>(features, dst_masks);
    scan_kernel<<<dim3(Ee / 8, Bb), 256>>>(unroll_mat);
    accum_kernel<<<dim3(NTILES, Bb), 256>>>(occurrences, out);
}

// round 15
// speedup vs baseline: 1.0689x; 1.0255x over previous
#include <cuda_runtime.h>
#include <stdint.h>

#define Bb 8
#define NF 128
#define Ee 3072
#define Uu 4096
#define UT 64
#define NTILES (Uu / UT)          // 64
#define BK 64                     // per-class list capacity (expected ~17, 8 classes)

#define VL_BLOCKS Bb                              // 8 vlist blocks (first)
#define TR_BLOCKS (Bb * (Ee / 32) * (NF / 32))    // 3072 transpose blocks
#define SC_BLOCKS (Bb * (Ee / 8))                 // 3072 scan blocks
#define AC_BLOCKS (Bb * NTILES)                   // 512 accum blocks
#define SCAN_PER_BATCH (Ee / 8)                   // 384

// Scratch (static __device__ arrays; no allocation at runtime)
__device__ unsigned short g_vlist[Bb * Ee];                 // v index of e-th true dst slot
__device__ float g_ft[(size_t)Bb * Ee * NF];                // transposed features [b][e][n]
__device__ int   g_cnt[Bb * NTILES * 8];                    // per-(b,utile,class) hit counts
__device__ uint2 g_list[(size_t)Bb * NTILES * 8 * BK];      // entries: (e<<6|ulocal, w bits)
__device__ int   g_batchdone[Bb];                           // scan blocks retired per batch

// ---------------- kernel 1: vlist blocks (first 8) + float4 transpose blocks ----------------
__global__ __launch_bounds__(256) void prep_kernel(
    const float* __restrict__ features, const unsigned char* __restrict__ dstraw) {
    int bid = blockIdx.x;
    int tid = threadIdx.x;

    if (bid < VL_BLOCKS) {
        // ---- vlist for batch bid: prefix-scan dst mask; zero counters/flags ----
        __shared__ int s_nz;
        __shared__ int wsum[8];
        int b = bid;
        // reset this batch's 512 class counters + done flag (graph-replay safe)
        g_cnt[b * NTILES * 8 + tid] = 0;
        g_cnt[b * NTILES * 8 + 256 + tid] = 0;
        if (tid == 0) g_batchdone[b] = 0;

        // dtype detection: nonzero bytes sampled from first 4096 bytes.
        if (tid == 0) s_nz = 0;
        __syncthreads();
        int nz = (dstraw[tid] != 0) + (dstraw[1024 + tid] != 0) +
                 (dstraw[2048 + tid] != 0) + (dstraw[3072 + tid] != 0);
#pragma unroll
        for (int off = 16; off; off >>= 1) nz += __shfl_down_sync(0xffffffffu, nz, off);
        if ((tid & 31) == 0) atomicAdd(&s_nz, nz);
        __syncthreads();
        bool is_byte = (s_nz > 512);

        // each thread handles 16 consecutive mask elements
        int v0 = tid * 16;
        unsigned m16 = 0;
        if (is_byte) {
            uint4 r = *(const uint4*)(dstraw + (size_t)b * Uu + v0);
            unsigned wds[4] = {r.x, r.y, r.z, r.w};
#pragma unroll
            for (int w = 0; w < 4; ++w)
#pragma unroll
                for (int k = 0; k < 4; ++k)
                    if ((wds[w] >> (8 * k)) & 0xffu) m16 |= 1u << (w * 4 + k);
        } else {
            const uint4* d32 = (const uint4*)dstraw;
#pragma unroll
            for (int w = 0; w < 4; ++w) {
                uint4 r = d32[((size_t)b * Uu + v0) / 4 + w];
                if (r.x) m16 |= 1u << (w * 4 + 0);
                if (r.y) m16 |= 1u << (w * 4 + 1);
                if (r.z) m16 |= 1u << (w * 4 + 2);
                if (r.w) m16 |= 1u << (w * 4 + 3);
            }
        }
        int c = __popc(m16);
        int incl = c;
#pragma unroll
        for (int off = 1; off < 32; off <<= 1) {
            int y = __shfl_up_sync(0xffffffffu, incl, off);
            if ((tid & 31) >= off) incl += y;
        }
        if ((tid & 31) == 31) wsum[tid >> 5] = incl;
        __syncthreads();
        if (tid < 8) {
            int s = wsum[tid];
#pragma unroll
            for (int off = 1; off < 8; off <<= 1) {
                int y = __shfl_up_sync(0xffu, s, off);
                if (tid >= off) s += y;
            }
            wsum[tid] = s;
        }
        __syncthreads();
        int base = ((tid >> 5) ? wsum[(tid >> 5) - 1] : 0) + incl - c;
#pragma unroll
        for (int k = 0; k < 16; ++k) {
            if ((m16 >> k) & 1u) {
                if (base < Ee) g_vlist[b * Ee + base] = (unsigned short)(v0 + k);
                ++base;
            }
        }
        return;
    }

    // ---- transpose features [B,NF,E] -> g_ft [B,E,NF], 128-bit both sides ----
    __shared__ float tile[32][33];
    int tb  = bid - VL_BLOCKS;
    int b   = tb / 384;                 // 384 = (Ee/32)*(NF/32)
    int rem = tb % 384;
    int e0  = (rem % 96) * 32;
    int n0  = (rem / 96) * 32;
    {
        int n_idx = tid >> 3;
        int e_idx = (tid & 7) * 4;
        float4 v = *(const float4*)(features +
                      (size_t)b * NF * Ee + (size_t)(n0 + n_idx) * Ee + e0 + e_idx);
        tile[e_idx + 0][n_idx] = v.x;
        tile[e_idx + 1][n_idx] = v.y;
        tile[e_idx + 2][n_idx] = v.z;
        tile[e_idx + 3][n_idx] = v.w;
    }
    __syncthreads();
    {
        int e_w = tid >> 3;
        int n_w = (tid & 7) * 4;
        float4 v;
        v.x = tile[e_w][n_w + 0];
        v.y = tile[e_w][n_w + 1];
        v.z = tile[e_w][n_w + 2];
        v.w = tile[e_w][n_w + 3];
        *(float4*)(g_ft + (size_t)b * Ee * NF + (size_t)(e0 + e_w) * NF + n0 + n_w) = v;
    }
}

// ------- kernel 2: scan blocks (first 3072) + accum tail blocks (last 512) -------
__global__ __launch_bounds__(256) void scan_accum_kernel(
    const float* __restrict__ W, const float* __restrict__ occ, float* __restrict__ out) {
    __shared__ float s_acc[UT * 132];     // accum role only (scan role leaves it unused)
    __shared__ float s_rocc[UT];

    int bid = blockIdx.x;
    int tid = threadIdx.x;
    int warp = tid >> 5;
    int lane = tid & 31;

    if (bid < SC_BLOCKS) {
        // ---- scan: one warp streams one full 16KB row of W ----
        int b    = bid / SCAN_PER_BATCH;
        int eblk = bid % SCAN_PER_BATCH;
        int e    = eblk * 8 + warp;

        int v = g_vlist[b * Ee + e];
        const float4* row = (const float4*)(W + ((size_t)b * Uu + v) * Uu);

#pragma unroll 1
        for (int i0 = 0; i0 < 32; i0 += 8) {
            float4 x[8];
#pragma unroll
            for (int j = 0; j < 8; ++j)
                x[j] = __ldcs(&row[(i0 + j) * 32 + lane]);   // streaming

#define ORW(v4) (__float_as_uint((v4).x) | __float_as_uint((v4).y) | \
                 __float_as_uint((v4).z) | __float_as_uint((v4).w))
            unsigned any = (ORW(x[0]) | ORW(x[1]) | ORW(x[2]) | ORW(x[3])) |
                           (ORW(x[4]) | ORW(x[5]) | ORW(x[6]) | ORW(x[7]));
            if (any) {
#pragma unroll
                for (int j = 0; j < 8; ++j) {
                    float vals[4] = {x[j].x, x[j].y, x[j].z, x[j].w};
#pragma unroll
                    for (int k = 0; k < 4; ++k) {
                        if (__float_as_uint(vals[k]) != 0u) {
                            int u   = ((i0 + j) * 32 + lane) * 4 + k;
                            int ut  = u >> 6;
                            int cls = u & 7;
                            int slot = (b * NTILES + ut) * 8 + cls;
                            int pos = atomicAdd(&g_cnt[slot], 1);
                            if (pos < BK)
                                g_list[(size_t)slot * BK + pos] =
                                    make_uint2(((unsigned)e << 6) | (unsigned)(u & 63),
                                               __float_as_uint(vals[k]));
                        }
                    }
                }
            }
        }
        // publish retirement for this batch
        __syncthreads();
        if (tid == 0) {
            __threadfence();
            atomicAdd(&g_batchdone[b], 1);
        }
        return;
    }

    // ---- accum tail block: wait for its batch's scan to finish, then drain ----
    int ab  = bid - SC_BLOCKS;
    int b   = ab / NTILES;      // batch-major: batch-0 accums first (matches scan order)
    int ut  = ab % NTILES;
    int u0  = ut * UT;
    int n0  = lane * 4;

    // overlap what we can before the wait: zero-init (float4) + occ
    float4 z4 = make_float4(0.f, 0.f, 0.f, 0.f);
    for (int i = tid; i < UT * 33; i += 256) ((float4*)s_acc)[i] = z4;
    if (tid < UT) s_rocc[tid] = 1.0f / occ[(size_t)b * Uu + u0 + tid];

    if (tid == 0) {
        while (atomicAdd(&g_batchdone[b], 0) < SCAN_PER_BATCH) __nanosleep(200);
        __threadfence();
    }
    __syncthreads();    // doubles as init barrier + wait broadcast

    int m_raw = g_cnt[(b * NTILES + ut) * 8 + warp];

    // warp w drains its class list directly from global (uniform broadcast loads).
    // class-disjoint u across warps + lane-disjoint n0 within warp = no races.
    {
        const float* ftb = g_ft + (size_t)b * Ee * NF + n0;
        const uint2* clist = &g_list[(size_t)((b * NTILES + ut) * 8 + warp) * BK];
        int m = min(m_raw, BK);

#define APPLY(ee, ff)                                                     \
        {                                                                 \
            int u = (ee).x & 63;                                          \
            float w = __uint_as_float((ee).y);                            \
            float4* ap = (float4*)&s_acc[u * 132 + n0];                   \
            float4 a = *ap;                                               \
            a.x += w * (ff).x; a.y += w * (ff).y;                         \
            a.z += w * (ff).z; a.w += w * (ff).w;                         \
            *ap = a;                                                      \
        }

        int j = 0;
        for (; j + 8 <= m; j += 8) {     // 8-wide gather batching (MLP=8)
            uint2 ee[8];
            float4 ff[8];
#pragma unroll
            for (int k = 0; k < 8; ++k) ee[k] = __ldg(&clist[j + k]);
#pragma unroll
            for (int k = 0; k < 8; ++k)
                ff[k] = *(const float4*)&ftb[(size_t)(ee[k].x >> 6) * NF];
#pragma unroll
            for (int k = 0; k < 8; ++k) APPLY(ee[k], ff[k]);
        }
        if (j < m) {                     // tail: up to 7 entries, still batched
            uint2 ee[8];
            float4 ff[8];
            int r = m - j;
#pragma unroll
            for (int k = 0; k < 8; ++k) if (k < r) ee[k] = __ldg(&clist[j + k]);
#pragma unroll
            for (int k = 0; k < 8; ++k)
                if (k < r) ff[k] = *(const float4*)&ftb[(size_t)(ee[k].x >> 6) * NF];
#pragma unroll
            for (int k = 0; k < 8; ++k) if (k < r) APPLY(ee[k], ff[k]);
        }
    }
    __syncthreads();

    // epilogue: multiply by 1/occ, coalesced store
    int u  = tid & (UT - 1);
    int nb = tid >> 6;          // 0..3
    float r = s_rocc[u];
#pragma unroll
    for (int i = 0; i < (UT * NF / 256); ++i) {   // 32 iters
        int n = 4 * i + nb;
        out[((size_t)(b * NF + n)) * Uu + u0 + u] = s_acc[u * 132 + n] * r;
    }
}

extern "C" void kernel_launch(void* const* d_in, const int* in_sizes, int n_in,
                              void* d_out, int out_size) {
    const float* features          = (const float*)d_in[0];
    const float* unroll_mat        = (const float*)d_in[1];
    const float* occurrences       = (const float*)d_in[2];
    const unsigned char* dst_masks = (const unsigned char*)d_in[3];
    float* out = (float*)d_out;

    prep_kernel<<<VL_BLOCKS + TR_BLOCKS, 256>>>(features, dst_masks);
    scan_accum_kernel<<<SC_BLOCKS + AC_BLOCKS, 256>>>(unroll_mat, occurrences, out);
}